// round 7
// baseline (speedup 1.0000x reference)
#include <cuda_runtime.h>
#include <cuda_bf16.h>
#include <cstdint>

#define NN 50000
#define NE 600000
#define HID 128
#define NG 128
#define NC 10
#define NL 4
#define NW 9          // 1 emb + 2*NL layer weights

// ---------------- scratch ----------------
__device__ __align__(16) float g_h[NN * HID];
__device__ __align__(16) float g_y1[NN * HID];
__device__ __align__(16) float g_y2[NN * HID];
__device__ float g_colsum[HID];
__device__ float g_colsq[HID];
__device__ __align__(16) float g_sc1[HID], g_sh1[HID], g_sc2[HID], g_sh2[HID];
__device__ __align__(16) float g_pooled[(NL + 1) * NG * HID];
__device__ float g_counts[NG];
// CSR
__device__ int g_cnt[NN];
__device__ int g_rowptr[NN + 1];
__device__ int g_cursor[NN];
__device__ int g_csr[NE];
// pre-split weights, transposed [n][k], bf16 hi/lo
__device__ __align__(16) __nv_bfloat16 g_whi[NW * HID * HID];
__device__ __align__(16) __nv_bfloat16 g_wlo[NW * HID * HID];

// ---------------- helpers ----------------
__device__ __forceinline__ uint32_t smem_u32(const void* p) {
    uint32_t a;
    asm("{ .reg .u64 t; cvta.to.shared.u64 t, %1; cvt.u32.u64 %0, t; }" : "=r"(a) : "l"(p));
    return a;
}
__device__ __forceinline__ void ldsm4(uint32_t* r, uint32_t addr) {
    asm volatile("ldmatrix.sync.aligned.m8n8.x4.shared.b16 {%0,%1,%2,%3}, [%4];"
                 : "=r"(r[0]), "=r"(r[1]), "=r"(r[2]), "=r"(r[3]) : "r"(addr));
}
__device__ __forceinline__ void mma16816(float* c, const uint32_t* a, const uint32_t* b) {
    asm volatile(
        "mma.sync.aligned.m16n8k16.row.col.f32.bf16.bf16.f32 "
        "{%0,%1,%2,%3}, {%4,%5,%6,%7}, {%8,%9}, {%0,%1,%2,%3};"
        : "+f"(c[0]), "+f"(c[1]), "+f"(c[2]), "+f"(c[3])
        : "r"(a[0]), "r"(a[1]), "r"(a[2]), "r"(a[3]), "r"(b[0]), "r"(b[1]));
}

// tile leading dim: 128+8 -> 272B rows, conflict-free LDSM
#define LDT 136
#define TILE_BYTES (128 * LDT * 2)
#define SM_TOT (4 * TILE_BYTES)

// ---------------- weight pre-split (all 9 matrices in one launch) ----------------
__global__ void wconv_k(const float* __restrict__ emb_w,
                        const float* __restrict__ w1,
                        const float* __restrict__ w2)
{
    const int m = blockIdx.y;
    const float* W = (m == 0) ? emb_w
                   : ((m & 1) ? w1 + (size_t)((m - 1) >> 1) * HID * HID
                              : w2 + (size_t)((m >> 1) - 1) * HID * HID);
    const int o = blockIdx.x * 1024 + threadIdx.x;
    if (o >= HID * HID) return;
    const int n = o >> 7, k = o & 127;
    const float w = __ldg(&W[k * 128 + n]);
    const __nv_bfloat16 h = __float2bfloat16(w);
    g_whi[(size_t)m * HID * HID + o] = h;
    g_wlo[(size_t)m * HID * HID + o] = __float2bfloat16(w - __bfloat162float(h));
}

// ---------------- tensor GEMM: out[n,128] = f(A)[n,128] @ W[128,128] + bias ----------------
// MODE 0: a = A
// MODE 1: a = (1+eps)*h[row] + sum_{u->row} h[u]   (fused CSR gather; A unused)
// MODE 2: a = relu(A*bnsc + bnsh)
template <int MODE, bool STATS>
__global__ void __launch_bounds__(256) tgemm_k(
    const float* __restrict__ A,
    const float* __restrict__ bnsc, const float* __restrict__ bnsh,
    const float* __restrict__ epsPtr, int layer,
    int widx, const float* __restrict__ bias,
    float* __restrict__ out, int n)
{
    extern __shared__ char smem[];
    __nv_bfloat16* Ahi = (__nv_bfloat16*)(smem);
    __nv_bfloat16* Alo = (__nv_bfloat16*)(smem + TILE_BYTES);
    __nv_bfloat16* Bhi = (__nv_bfloat16*)(smem + 2 * TILE_BYTES);
    __nv_bfloat16* Blo = (__nv_bfloat16*)(smem + 3 * TILE_BYTES);
    __shared__ float s_sum[128], s_sq[128];

    const int tid = threadIdx.x;
    const int lane = tid & 31;
    const int wid = tid >> 5;
    const int wm = wid & 3;
    const int wn = wid >> 2;
    const int row0 = blockIdx.x * 128;

    if (STATS && tid < 128) { s_sum[tid] = 0.f; s_sq[tid] = 0.f; }

    // ---- A tile: thread owns row tid/2, 64-col half; packed 16B smem stores ----
    {
        const int r = tid >> 1;
        const int row = row0 + r;
        const int cb = (tid & 1) * 64;
        const bool ok = (row < n);
        const float4* Ar = (const float4*)(A + (size_t)row * 128 + cb);
        int rp0 = 0, rp1 = 0;
        float oe = 1.0f;
        if (MODE == 1) {
            oe = 1.0f + epsPtr[layer];
            if (ok) { rp0 = g_rowptr[row]; rp1 = g_rowptr[row + 1]; }
        }
#pragma unroll 2
        for (int i = 0; i < 8; i++) {          // 8 elems per iter
            float v[8] = {0, 0, 0, 0, 0, 0, 0, 0};
            if (ok) {
                if (MODE == 1) {
                    const float4* hr = (const float4*)(g_h + (size_t)row * 128 + cb + i * 8);
                    float4 a0 = hr[0], a1 = hr[1];
                    v[0] = oe * a0.x; v[1] = oe * a0.y; v[2] = oe * a0.z; v[3] = oe * a0.w;
                    v[4] = oe * a1.x; v[5] = oe * a1.y; v[6] = oe * a1.z; v[7] = oe * a1.w;
                    for (int e = rp0; e < rp1; e++) {
                        const int s = g_csr[e];
                        const float4* p = (const float4*)(g_h + (size_t)s * 128 + cb + i * 8);
                        const float4 b0 = p[0], b1 = p[1];
                        v[0] += b0.x; v[1] += b0.y; v[2] += b0.z; v[3] += b0.w;
                        v[4] += b1.x; v[5] += b1.y; v[6] += b1.z; v[7] += b1.w;
                    }
                } else {
                    float4 a0 = Ar[2 * i], a1 = Ar[2 * i + 1];
                    v[0] = a0.x; v[1] = a0.y; v[2] = a0.z; v[3] = a0.w;
                    v[4] = a1.x; v[5] = a1.y; v[6] = a1.z; v[7] = a1.w;
                    if (MODE == 2) {
                        const float* sc = bnsc + cb + i * 8;
                        const float* sh = bnsh + cb + i * 8;
#pragma unroll
                        for (int u = 0; u < 8; u++)
                            v[u] = fmaxf(fmaf(v[u], sc[u], sh[u]), 0.f);
                    }
                }
            }
            __nv_bfloat16 hi[8], lo[8];
#pragma unroll
            for (int u = 0; u < 8; u++) {
                hi[u] = __float2bfloat16(v[u]);
                lo[u] = __float2bfloat16(v[u] - __bfloat162float(hi[u]));
            }
            const int base = r * LDT + cb + i * 8;
            *(float4*)&Ahi[base] = *(const float4*)hi;
            *(float4*)&Alo[base] = *(const float4*)lo;
        }
    }
    // ---- B tile: pure copy from pre-split transposed weights ----
    {
        const int r = tid >> 1;
        const int kc = (tid & 1) * 64;
        const float4* sh4 = (const float4*)(g_whi + (size_t)widx * HID * HID + r * 128 + kc);
        const float4* sl4 = (const float4*)(g_wlo + (size_t)widx * HID * HID + r * 128 + kc);
#pragma unroll
        for (int i = 0; i < 8; i++) {
            const int base = r * LDT + kc + i * 8;
            *(float4*)&Bhi[base] = sh4[i];
            *(float4*)&Blo[base] = sl4[i];
        }
    }
    __syncthreads();

    // ---- warp mma mainloop: 32x64 per warp ----
    float acc[2][8][4];
#pragma unroll
    for (int mt = 0; mt < 2; mt++)
#pragma unroll
        for (int j = 0; j < 8; j++)
#pragma unroll
            for (int u = 0; u < 4; u++) acc[mt][j][u] = 0.f;

    const uint32_t sAhi = smem_u32(Ahi), sAlo = smem_u32(Alo);
    const uint32_t sBhi = smem_u32(Bhi), sBlo = smem_u32(Blo);

    const int aRow = wm * 32 + (lane & 15);
    const int aCol = (lane >> 4) * 8;
    // B ldsm4 lane map: 16n x 16k -> two j fragments
    const int bR = wn * 64 + (lane & 7) + ((lane >> 3) & 1) * 8;
    const int bC = (lane >> 4) * 8;

#pragma unroll
    for (int ks = 0; ks < 8; ks++) {
        uint32_t ahi[2][4], alo[2][4], bhi[8][2], blo[8][2];
        const int kc = ks * 16;
#pragma unroll
        for (int mt = 0; mt < 2; mt++) {
            const uint32_t off = ((aRow + mt * 16) * LDT + kc + aCol) * 2;
            ldsm4(ahi[mt], sAhi + off);
            ldsm4(alo[mt], sAlo + off);
        }
#pragma unroll
        for (int jp = 0; jp < 4; jp++) {
            const uint32_t off = ((bR + jp * 16) * LDT + kc + bC) * 2;
            uint32_t th[4], tl[4];
            ldsm4(th, sBhi + off);
            ldsm4(tl, sBlo + off);
            bhi[2 * jp][0] = th[0];     bhi[2 * jp][1] = th[2];
            bhi[2 * jp + 1][0] = th[1]; bhi[2 * jp + 1][1] = th[3];
            blo[2 * jp][0] = tl[0];     blo[2 * jp][1] = tl[2];
            blo[2 * jp + 1][0] = tl[1]; blo[2 * jp + 1][1] = tl[3];
        }
#pragma unroll
        for (int mt = 0; mt < 2; mt++)
#pragma unroll
            for (int j = 0; j < 8; j++) {
                mma16816(acc[mt][j], ahi[mt], bhi[j]);
                mma16816(acc[mt][j], ahi[mt], blo[j]);
                mma16816(acc[mt][j], alo[mt], bhi[j]);
            }
    }

    // ---- epilogue: bias + store (+ fused column stats) ----
    float st[8][4];
    if (STATS) {
#pragma unroll
        for (int j = 0; j < 8; j++)
#pragma unroll
            for (int u = 0; u < 4; u++) st[j][u] = 0.f;
    }
#pragma unroll
    for (int mt = 0; mt < 2; mt++) {
        const int r_lo = row0 + wm * 32 + mt * 16 + (lane >> 2);
        const int r_hi = r_lo + 8;
#pragma unroll
        for (int j = 0; j < 8; j++) {
            const int c = wn * 64 + j * 8 + (lane & 3) * 2;
            const float b0 = bias[c], b1 = bias[c + 1];
            if (r_lo < n) {
                const float v0 = acc[mt][j][0] + b0, v1 = acc[mt][j][1] + b1;
                *(float2*)(out + (size_t)r_lo * 128 + c) = make_float2(v0, v1);
                if (STATS) {
                    st[j][0] += v0; st[j][1] += v1;
                    st[j][2] = fmaf(v0, v0, st[j][2]); st[j][3] = fmaf(v1, v1, st[j][3]);
                }
            }
            if (r_hi < n) {
                const float v0 = acc[mt][j][2] + b0, v1 = acc[mt][j][3] + b1;
                *(float2*)(out + (size_t)r_hi * 128 + c) = make_float2(v0, v1);
                if (STATS) {
                    st[j][0] += v0; st[j][1] += v1;
                    st[j][2] = fmaf(v0, v0, st[j][2]); st[j][3] = fmaf(v1, v1, st[j][3]);
                }
            }
        }
    }
    if (STATS) {
#pragma unroll
        for (int j = 0; j < 8; j++)
#pragma unroll
            for (int u = 0; u < 4; u++) {
                st[j][u] += __shfl_xor_sync(0xFFFFFFFF, st[j][u], 4);
                st[j][u] += __shfl_xor_sync(0xFFFFFFFF, st[j][u], 8);
                st[j][u] += __shfl_xor_sync(0xFFFFFFFF, st[j][u], 16);
            }
        if (lane < 4) {
#pragma unroll
            for (int j = 0; j < 8; j++) {
                const int c = wn * 64 + j * 8 + lane * 2;
                atomicAdd(&s_sum[c], st[j][0]);
                atomicAdd(&s_sum[c + 1], st[j][1]);
                atomicAdd(&s_sq[c], st[j][2]);
                atomicAdd(&s_sq[c + 1], st[j][3]);
            }
        }
        __syncthreads();
        if (tid < 128) {
            atomicAdd(&g_colsum[tid], s_sum[tid]);
            atomicAdd(&g_colsq[tid], s_sq[tid]);
        }
    }
}

// ---------------- finalize BN ----------------
__global__ void bnfin_k(const float* __restrict__ gam, const float* __restrict__ bet,
                        float* __restrict__ sc, float* __restrict__ sh)
{
    const int c = threadIdx.x;
    const float inv_n = 1.0f / (float)NN;
    const float m = g_colsum[c] * inv_n;
    const float var = g_colsq[c] * inv_n - m * m;
    const float s = gam[c] * rsqrtf(var + 1e-5f);
    sc[c] = s;
    sh[c] = bet[c] - m * s;
    g_colsum[c] = 0.0f;
    g_colsq[c] = 0.0f;
}

// ---------------- CSR build ----------------
__global__ void hist_k(const int* __restrict__ dst)
{
    const int e = blockIdx.x * 256 + threadIdx.x;
    if (e < NE) atomicAdd(&g_cnt[dst[e]], 1);
}

__global__ void __launch_bounds__(1024) scan_k()
{
    __shared__ int sm[1024];
    const int t = threadIdx.x;
    const int per = (NN + 1023) / 1024;
    const int beg = t * per;
    const int end = min(beg + per, NN);
    int s = 0;
    for (int i = beg; i < end; i++) s += g_cnt[i];
    sm[t] = s;
    __syncthreads();
    for (int off = 1; off < 1024; off <<= 1) {
        int v = (t >= off) ? sm[t - off] : 0;
        __syncthreads();
        sm[t] += v;
        __syncthreads();
    }
    int run = sm[t] - s;   // exclusive prefix
    for (int i = beg; i < end; i++) {
        const int c = g_cnt[i];
        g_rowptr[i] = run;
        g_cursor[i] = run;
        run += c;
    }
    if (t == 1023) g_rowptr[NN] = sm[1023];
}

__global__ void fill_k(const int* __restrict__ src, const int* __restrict__ dst)
{
    const int e = blockIdx.x * 256 + threadIdx.x;
    if (e >= NE) return;
    const int pos = atomicAdd(&g_cursor[dst[e]], 1);
    g_csr[pos] = src[e];
}

// ---------------- residual update + pooling ----------------
template <bool UPDATE>
__global__ void __launch_bounds__(256) pool_k(const float* __restrict__ y2,
                                              const float* __restrict__ sc,
                                              const float* __restrict__ sh,
                                              const int* __restrict__ batch,
                                              float* __restrict__ pooled)
{
    const int node = blockIdx.x * 8 + (threadIdx.x >> 5);
    if (node >= NN) return;
    const int lane = threadIdx.x & 31;
    const int g = batch[node];
    float4 hv = *reinterpret_cast<const float4*>(&g_h[node * 128 + lane * 4]);
    if (UPDATE) {
        const float4 yv = *reinterpret_cast<const float4*>(&y2[node * 128 + lane * 4]);
        const float4 scv = *reinterpret_cast<const float4*>(&sc[lane * 4]);
        const float4 shv = *reinterpret_cast<const float4*>(&sh[lane * 4]);
        hv.x += fmaxf(fmaf(yv.x, scv.x, shv.x), 0.0f);
        hv.y += fmaxf(fmaf(yv.y, scv.y, shv.y), 0.0f);
        hv.z += fmaxf(fmaf(yv.z, scv.z, shv.z), 0.0f);
        hv.w += fmaxf(fmaf(yv.w, scv.w, shv.w), 0.0f);
        *reinterpret_cast<float4*>(&g_h[node * 128 + lane * 4]) = hv;
    }
    atomicAdd(reinterpret_cast<float4*>(&pooled[g * 128 + lane * 4]), hv);
}

// ---------------- counts ----------------
__global__ void counts_k(const int* __restrict__ batch)
{
    const int i = blockIdx.x * 256 + threadIdx.x;
    if (i < NN) atomicAdd(&g_counts[batch[i]], 1.0f);
}

// ---------------- heads ----------------
__global__ void head_k(const float* __restrict__ pw, const float* __restrict__ pb,
                       float* __restrict__ out)
{
    const int g = blockIdx.x;
    const int c = threadIdx.x;
    if (c >= NC) return;
    const float inv_cnt = 1.0f / fmaxf(g_counts[g], 1.0f);
    float acc = 0.0f;
#pragma unroll
    for (int l = 0; l <= NL; l++) {
        const float* p = &g_pooled[(l * NG + g) * HID];
        float a = 0.0f;
#pragma unroll 8
        for (int f = 0; f < HID; f++)
            a = fmaf(p[f], pw[(l * HID + f) * NC + c], a);
        acc += a * inv_cnt + pb[l * NC + c];
    }
    out[g * NC + c] = acc;
}

// ---------------- launch ----------------
extern "C" void kernel_launch(void* const* d_in, const int* in_sizes, int n_in,
                              void* d_out, int out_size)
{
    const float* x     = (const float*)d_in[0];
    const int*   ei    = (const int*)d_in[1];
    const int*   batch = (const int*)d_in[2];
    const float* emb_w = (const float*)d_in[3];
    const float* emb_b = (const float*)d_in[4];
    const float* eps   = (const float*)d_in[5];
    const float* w1    = (const float*)d_in[6];
    const float* b1    = (const float*)d_in[7];
    const float* bn1g  = (const float*)d_in[8];
    const float* bn1b  = (const float*)d_in[9];
    const float* w2    = (const float*)d_in[10];
    const float* b2    = (const float*)d_in[11];
    const float* bng   = (const float*)d_in[12];
    const float* bnb   = (const float*)d_in[13];
    const float* pw    = (const float*)d_in[14];
    const float* pb    = (const float*)d_in[15];
    float*       out   = (float*)d_out;

    void *p_h, *p_y1, *p_y2, *p_pooled, *p_counts, *p_colsum, *p_colsq;
    void *p_sc1, *p_sh1, *p_sc2, *p_sh2, *p_cnt;
    cudaGetSymbolAddress(&p_h,      g_h);
    cudaGetSymbolAddress(&p_y1,     g_y1);
    cudaGetSymbolAddress(&p_y2,     g_y2);
    cudaGetSymbolAddress(&p_pooled, g_pooled);
    cudaGetSymbolAddress(&p_counts, g_counts);
    cudaGetSymbolAddress(&p_colsum, g_colsum);
    cudaGetSymbolAddress(&p_colsq,  g_colsq);
    cudaGetSymbolAddress(&p_sc1,    g_sc1);
    cudaGetSymbolAddress(&p_sh1,    g_sh1);
    cudaGetSymbolAddress(&p_sc2,    g_sc2);
    cudaGetSymbolAddress(&p_sh2,    g_sh2);
    cudaGetSymbolAddress(&p_cnt,    g_cnt);

    cudaFuncSetAttribute(tgemm_k<0, false>, cudaFuncAttributeMaxDynamicSharedMemorySize, SM_TOT);
    cudaFuncSetAttribute(tgemm_k<1, true>,  cudaFuncAttributeMaxDynamicSharedMemorySize, SM_TOT);
    cudaFuncSetAttribute(tgemm_k<2, true>,  cudaFuncAttributeMaxDynamicSharedMemorySize, SM_TOT);

    cudaMemsetAsync(p_pooled, 0, sizeof(float) * (NL + 1) * NG * HID);
    cudaMemsetAsync(p_counts, 0, sizeof(float) * NG);
    cudaMemsetAsync(p_colsum, 0, sizeof(float) * HID);
    cudaMemsetAsync(p_colsq,  0, sizeof(float) * HID);
    cudaMemsetAsync(p_cnt,    0, sizeof(int) * NN);

    // pre-split all 9 weights in one launch: m=0 emb, m=1+2l w1[l], m=2+2l w2[l]
    wconv_k<<<dim3(16, NW), 1024>>>(emb_w, w1, w2);

    // CSR build (by dst, storing src)
    hist_k<<<(NE + 255) / 256, 256>>>(ei + NE);
    scan_k<<<1, 1024>>>();
    fill_k<<<(NE + 255) / 256, 256>>>(ei, ei + NE);

    counts_k<<<(NN + 255) / 256, 256>>>(batch);

    const int GB = (NN + 127) / 128;

    // embedding
    tgemm_k<0, false><<<GB, 256, SM_TOT>>>(x, nullptr, nullptr, nullptr, 0,
                                           0, emb_b, (float*)p_h, NN);
    pool_k<false><<<(NN + 7) / 8, 256>>>(nullptr, nullptr, nullptr, batch, (float*)p_pooled);

    for (int l = 0; l < NL; l++) {
        // y1 = ((1+eps)h + CSR-gather(h)) @ w1 + b1   (gather fused into A-load)
        tgemm_k<1, true><<<GB, 256, SM_TOT>>>(nullptr, nullptr, nullptr, eps, l,
                                              1 + 2 * l, b1 + l * HID, (float*)p_y1, NN);
        bnfin_k<<<1, 128>>>(bn1g + l * HID, bn1b + l * HID, (float*)p_sc1, (float*)p_sh1);

        tgemm_k<2, true><<<GB, 256, SM_TOT>>>((const float*)p_y1, (const float*)p_sc1,
                                              (const float*)p_sh1, nullptr, 0,
                                              2 + 2 * l, b2 + l * HID, (float*)p_y2, NN);
        bnfin_k<<<1, 128>>>(bng + l * HID, bnb + l * HID, (float*)p_sc2, (float*)p_sh2);

        pool_k<true><<<(NN + 7) / 8, 256>>>((const float*)p_y2, (const float*)p_sc2,
                                            (const float*)p_sh2, batch,
                                            (float*)p_pooled + (size_t)(l + 1) * NG * HID);
    }

    head_k<<<NG, 32>>>(pw, pb, out);
}

// round 8
// speedup vs baseline: 1.4025x; 1.4025x over previous
#include <cuda_runtime.h>
#include <cuda_bf16.h>
#include <cstdint>

#define NN 50000
#define NE 600000
#define HID 128
#define NG 128
#define NC 10
#define NL 4
#define NW 9          // 1 emb + 2*NL layer weights

// ---------------- scratch ----------------
__device__ __align__(16) float g_h[NN * HID];
__device__ __align__(16) float g_agg[NN * HID];
__device__ __align__(16) float g_y1[NN * HID];
__device__ __align__(16) float g_y2[NN * HID];
__device__ float g_colsum[HID];
__device__ float g_colsq[HID];
__device__ __align__(16) float g_sc1[HID], g_sh1[HID], g_sc2[HID], g_sh2[HID];
__device__ __align__(16) float g_pooled[(NL + 1) * NG * HID];
// CSR + graph boundaries
__device__ int g_cnt[NN];
__device__ int g_rowptr[NN + 1];
__device__ int g_cursor[NN];
__device__ int g_csr[NE];
__device__ int g_goff[NG + 1];
// pre-split weights, transposed [n][k], bf16 hi/lo
__device__ __align__(16) __nv_bfloat16 g_whi[NW * HID * HID];
__device__ __align__(16) __nv_bfloat16 g_wlo[NW * HID * HID];

// ---------------- helpers ----------------
__device__ __forceinline__ uint32_t smem_u32(const void* p) {
    uint32_t a;
    asm("{ .reg .u64 t; cvta.to.shared.u64 t, %1; cvt.u32.u64 %0, t; }" : "=r"(a) : "l"(p));
    return a;
}
__device__ __forceinline__ void ldsm4(uint32_t* r, uint32_t addr) {
    asm volatile("ldmatrix.sync.aligned.m8n8.x4.shared.b16 {%0,%1,%2,%3}, [%4];"
                 : "=r"(r[0]), "=r"(r[1]), "=r"(r[2]), "=r"(r[3]) : "r"(addr));
}
__device__ __forceinline__ void mma16816(float* c, const uint32_t* a, const uint32_t* b) {
    asm volatile(
        "mma.sync.aligned.m16n8k16.row.col.f32.bf16.bf16.f32 "
        "{%0,%1,%2,%3}, {%4,%5,%6,%7}, {%8,%9}, {%0,%1,%2,%3};"
        : "+f"(c[0]), "+f"(c[1]), "+f"(c[2]), "+f"(c[3])
        : "r"(a[0]), "r"(a[1]), "r"(a[2]), "r"(a[3]), "r"(b[0]), "r"(b[1]));
}

// tile leading dim: 128+8 -> 272B rows, conflict-free LDSM
#define LDT 136
#define TILE_BYTES (128 * LDT * 2)
#define SM_TOT (4 * TILE_BYTES)

// ---------------- weight pre-split (all 9 matrices in one launch) ----------------
__global__ void wconv_k(const float* __restrict__ emb_w,
                        const float* __restrict__ w1,
                        const float* __restrict__ w2)
{
    const int m = blockIdx.y;
    const float* W = (m == 0) ? emb_w
                   : ((m & 1) ? w1 + (size_t)((m - 1) >> 1) * HID * HID
                              : w2 + (size_t)((m >> 1) - 1) * HID * HID);
    const int o = blockIdx.x * 1024 + threadIdx.x;
    if (o >= HID * HID) return;
    const int n = o >> 7, k = o & 127;
    const float w = __ldg(&W[k * 128 + n]);
    const __nv_bfloat16 h = __float2bfloat16(w);
    g_whi[(size_t)m * HID * HID + o] = h;
    g_wlo[(size_t)m * HID * HID + o] = __float2bfloat16(w - __bfloat162float(h));
}

// ---------------- tensor GEMM: out[n,128] = f(A)[n,128] @ W[128,128] + bias ----------------
// MODE 0: a = A ; MODE 2: a = relu(A*bnsc + bnsh)
template <int MODE, bool STATS>
__global__ void __launch_bounds__(256) tgemm_k(
    const float* __restrict__ A,
    const float* __restrict__ bnsc, const float* __restrict__ bnsh,
    int widx, const float* __restrict__ bias,
    float* __restrict__ out, int n)
{
    extern __shared__ char smem[];
    __nv_bfloat16* Ahi = (__nv_bfloat16*)(smem);
    __nv_bfloat16* Alo = (__nv_bfloat16*)(smem + TILE_BYTES);
    __nv_bfloat16* Bhi = (__nv_bfloat16*)(smem + 2 * TILE_BYTES);
    __nv_bfloat16* Blo = (__nv_bfloat16*)(smem + 3 * TILE_BYTES);
    __shared__ float s_sum[128], s_sq[128];

    const int tid = threadIdx.x;
    const int lane = tid & 31;
    const int wid = tid >> 5;
    const int wm = wid & 3;
    const int wn = wid >> 2;
    const int row0 = blockIdx.x * 128;

    if (STATS && tid < 128) { s_sum[tid] = 0.f; s_sq[tid] = 0.f; }

    // ---- A tile: thread owns row tid/2, 64-col half; packed 16B smem stores ----
    {
        const int r = tid >> 1;
        const int row = row0 + r;
        const int cb = (tid & 1) * 64;
        const float4* Ar = (const float4*)(A + (size_t)row * 128 + cb);
#pragma unroll 2
        for (int i = 0; i < 8; i++) {
            float v[8] = {0, 0, 0, 0, 0, 0, 0, 0};
            if (row < n) {
                float4 a0 = Ar[2 * i], a1 = Ar[2 * i + 1];
                v[0] = a0.x; v[1] = a0.y; v[2] = a0.z; v[3] = a0.w;
                v[4] = a1.x; v[5] = a1.y; v[6] = a1.z; v[7] = a1.w;
                if (MODE == 2) {
                    const float* sc = bnsc + cb + i * 8;
                    const float* sh = bnsh + cb + i * 8;
#pragma unroll
                    for (int u = 0; u < 8; u++)
                        v[u] = fmaxf(fmaf(v[u], sc[u], sh[u]), 0.f);
                }
            }
            __nv_bfloat16 hi[8], lo[8];
#pragma unroll
            for (int u = 0; u < 8; u++) {
                hi[u] = __float2bfloat16(v[u]);
                lo[u] = __float2bfloat16(v[u] - __bfloat162float(hi[u]));
            }
            const int base = r * LDT + cb + i * 8;
            *(float4*)&Ahi[base] = *(const float4*)hi;
            *(float4*)&Alo[base] = *(const float4*)lo;
        }
    }
    // ---- B tile: pure copy from pre-split transposed weights ----
    {
        const int r = tid >> 1;
        const int kc = (tid & 1) * 64;
        const float4* sh4 = (const float4*)(g_whi + (size_t)widx * HID * HID + r * 128 + kc);
        const float4* sl4 = (const float4*)(g_wlo + (size_t)widx * HID * HID + r * 128 + kc);
#pragma unroll
        for (int i = 0; i < 8; i++) {
            const int base = r * LDT + kc + i * 8;
            *(float4*)&Bhi[base] = sh4[i];
            *(float4*)&Blo[base] = sl4[i];
        }
    }
    __syncthreads();

    // ---- warp mma mainloop: 32x64 per warp ----
    float acc[2][8][4];
#pragma unroll
    for (int mt = 0; mt < 2; mt++)
#pragma unroll
        for (int j = 0; j < 8; j++)
#pragma unroll
            for (int u = 0; u < 4; u++) acc[mt][j][u] = 0.f;

    const uint32_t sAhi = smem_u32(Ahi), sAlo = smem_u32(Alo);
    const uint32_t sBhi = smem_u32(Bhi), sBlo = smem_u32(Blo);

    const int aRow = wm * 32 + (lane & 15);
    const int aCol = (lane >> 4) * 8;
    // B ldsm4 lane map: 16n x 16k -> two j fragments
    const int bR = wn * 64 + (lane & 7) + ((lane >> 3) & 1) * 8;
    const int bC = (lane >> 4) * 8;

#pragma unroll
    for (int ks = 0; ks < 8; ks++) {
        uint32_t ahi[2][4], alo[2][4], bhi[8][2], blo[8][2];
        const int kc = ks * 16;
#pragma unroll
        for (int mt = 0; mt < 2; mt++) {
            const uint32_t off = ((aRow + mt * 16) * LDT + kc + aCol) * 2;
            ldsm4(ahi[mt], sAhi + off);
            ldsm4(alo[mt], sAlo + off);
        }
#pragma unroll
        for (int jp = 0; jp < 4; jp++) {
            const uint32_t off = ((bR + jp * 16) * LDT + kc + bC) * 2;
            uint32_t th[4], tl[4];
            ldsm4(th, sBhi + off);
            ldsm4(tl, sBlo + off);
            bhi[2 * jp][0] = th[0];     bhi[2 * jp][1] = th[2];
            bhi[2 * jp + 1][0] = th[1]; bhi[2 * jp + 1][1] = th[3];
            blo[2 * jp][0] = tl[0];     blo[2 * jp][1] = tl[2];
            blo[2 * jp + 1][0] = tl[1]; blo[2 * jp + 1][1] = tl[3];
        }
#pragma unroll
        for (int mt = 0; mt < 2; mt++)
#pragma unroll
            for (int j = 0; j < 8; j++) {
                mma16816(acc[mt][j], ahi[mt], bhi[j]);
                mma16816(acc[mt][j], ahi[mt], blo[j]);
                mma16816(acc[mt][j], alo[mt], bhi[j]);
            }
    }

    // ---- epilogue: bias + store (+ fused column stats) ----
    float st[8][4];
    if (STATS) {
#pragma unroll
        for (int j = 0; j < 8; j++)
#pragma unroll
            for (int u = 0; u < 4; u++) st[j][u] = 0.f;
    }
#pragma unroll
    for (int mt = 0; mt < 2; mt++) {
        const int r_lo = row0 + wm * 32 + mt * 16 + (lane >> 2);
        const int r_hi = r_lo + 8;
#pragma unroll
        for (int j = 0; j < 8; j++) {
            const int c = wn * 64 + j * 8 + (lane & 3) * 2;
            const float b0 = bias[c], b1 = bias[c + 1];
            if (r_lo < n) {
                const float v0 = acc[mt][j][0] + b0, v1 = acc[mt][j][1] + b1;
                *(float2*)(out + (size_t)r_lo * 128 + c) = make_float2(v0, v1);
                if (STATS) {
                    st[j][0] += v0; st[j][1] += v1;
                    st[j][2] = fmaf(v0, v0, st[j][2]); st[j][3] = fmaf(v1, v1, st[j][3]);
                }
            }
            if (r_hi < n) {
                const float v0 = acc[mt][j][2] + b0, v1 = acc[mt][j][3] + b1;
                *(float2*)(out + (size_t)r_hi * 128 + c) = make_float2(v0, v1);
                if (STATS) {
                    st[j][0] += v0; st[j][1] += v1;
                    st[j][2] = fmaf(v0, v0, st[j][2]); st[j][3] = fmaf(v1, v1, st[j][3]);
                }
            }
        }
    }
    if (STATS) {
#pragma unroll
        for (int j = 0; j < 8; j++)
#pragma unroll
            for (int u = 0; u < 4; u++) {
                st[j][u] += __shfl_xor_sync(0xFFFFFFFF, st[j][u], 4);
                st[j][u] += __shfl_xor_sync(0xFFFFFFFF, st[j][u], 8);
                st[j][u] += __shfl_xor_sync(0xFFFFFFFF, st[j][u], 16);
            }
        if (lane < 4) {
#pragma unroll
            for (int j = 0; j < 8; j++) {
                const int c = wn * 64 + j * 8 + lane * 2;
                atomicAdd(&s_sum[c], st[j][0]);
                atomicAdd(&s_sum[c + 1], st[j][1]);
                atomicAdd(&s_sq[c], st[j][2]);
                atomicAdd(&s_sq[c + 1], st[j][3]);
            }
        }
        __syncthreads();
        if (tid < 128) {
            atomicAdd(&g_colsum[tid], s_sum[tid]);
            atomicAdd(&g_colsq[tid], s_sq[tid]);
        }
    }
}

// ---------------- finalize BN ----------------
__global__ void bnfin_k(const float* __restrict__ gam, const float* __restrict__ bet,
                        float* __restrict__ sc, float* __restrict__ sh)
{
    const int c = threadIdx.x;
    const float inv_n = 1.0f / (float)NN;
    const float m = g_colsum[c] * inv_n;
    const float var = g_colsq[c] * inv_n - m * m;
    const float s = gam[c] * rsqrtf(var + 1e-5f);
    sc[c] = s;
    sh[c] = bet[c] - m * s;
    g_colsum[c] = 0.0f;
    g_colsq[c] = 0.0f;
}

// ---------------- CSR build ----------------
__global__ void hist_k(const int* __restrict__ dst)
{
    const int e = blockIdx.x * 256 + threadIdx.x;
    if (e < NE) atomicAdd(&g_cnt[dst[e]], 1);
}

__global__ void __launch_bounds__(1024) scan_k()
{
    __shared__ int sm[1024];
    const int t = threadIdx.x;
    const int per = (NN + 1023) / 1024;
    const int beg = t * per;
    const int end = min(beg + per, NN);
    int s = 0;
    for (int i = beg; i < end; i++) s += g_cnt[i];
    sm[t] = s;
    __syncthreads();
    for (int off = 1; off < 1024; off <<= 1) {
        int v = (t >= off) ? sm[t - off] : 0;
        __syncthreads();
        sm[t] += v;
        __syncthreads();
    }
    int run = sm[t] - s;   // exclusive prefix
    for (int i = beg; i < end; i++) {
        const int c = g_cnt[i];
        g_rowptr[i] = run;
        g_cursor[i] = run;
        run += c;
    }
    if (t == 1023) g_rowptr[NN] = sm[1023];
}

__global__ void fill_k(const int* __restrict__ src, const int* __restrict__ dst)
{
    const int e = blockIdx.x * 256 + threadIdx.x;
    if (e >= NE) return;
    const int pos = atomicAdd(&g_cursor[dst[e]], 1);
    g_csr[pos] = src[e];
}

// ---------------- graph boundaries from sorted batch ----------------
__global__ void goff_k(const int* __restrict__ batch)
{
    const int i = blockIdx.x * 256 + threadIdx.x;
    if (i >= NN) return;
    const int b = batch[i];
    if (i == 0) {
        for (int g = 0; g <= b; g++) g_goff[g] = 0;
    } else {
        const int pb = batch[i - 1];
        for (int g = pb + 1; g <= b; g++) g_goff[g] = i;
    }
    if (i == NN - 1) {
        for (int g = b + 1; g <= NG; g++) g_goff[g] = NN;
    }
}

// ---------------- gather: agg[v] = (1+eps)*h[v] + sum_{u->v} h[u] ----------------
__global__ void __launch_bounds__(256) gather_k(const float* __restrict__ epsPtr, int layer)
{
    const int node = blockIdx.x * 8 + (threadIdx.x >> 5);
    if (node >= NN) return;
    const int lane = threadIdx.x & 31;
    const float oe = 1.0f + epsPtr[layer];
    const float4 hv = *(const float4*)(&g_h[(size_t)node * 128 + lane * 4]);
    float4 acc = make_float4(oe * hv.x, oe * hv.y, oe * hv.z, oe * hv.w);
    const int rp0 = g_rowptr[node], rp1 = g_rowptr[node + 1];
    for (int e = rp0; e < rp1; e++) {
        const int s = g_csr[e];
        const float4 v = *(const float4*)(&g_h[(size_t)s * 128 + lane * 4]);
        acc.x += v.x; acc.y += v.y; acc.z += v.z; acc.w += v.w;
    }
    *(float4*)(&g_agg[(size_t)node * 128 + lane * 4]) = acc;
}

// ---------------- atomic-free pooling (CTA per graph) ----------------
// UPDATE: h += relu(y2*sc+sh) first, then pooled[g] = sum of h over graph range.
template <bool UPDATE>
__global__ void __launch_bounds__(256) pool2_k(const float* __restrict__ y2,
                                               const float* __restrict__ sc,
                                               const float* __restrict__ sh,
                                               float* __restrict__ pooled)
{
    __shared__ float4 sm[8][32];
    const int g = blockIdx.x;
    const int beg = g_goff[g], end = g_goff[g + 1];
    const int lane = threadIdx.x & 31;
    const int w = threadIdx.x >> 5;

    float4 scv, shv;
    if (UPDATE) {
        scv = *(const float4*)(&sc[lane * 4]);
        shv = *(const float4*)(&sh[lane * 4]);
    }
    float4 acc = make_float4(0.f, 0.f, 0.f, 0.f);
    for (int r = beg + w; r < end; r += 8) {
        float4 hv = *(const float4*)(&g_h[(size_t)r * 128 + lane * 4]);
        if (UPDATE) {
            const float4 yv = *(const float4*)(&y2[(size_t)r * 128 + lane * 4]);
            hv.x += fmaxf(fmaf(yv.x, scv.x, shv.x), 0.f);
            hv.y += fmaxf(fmaf(yv.y, scv.y, shv.y), 0.f);
            hv.z += fmaxf(fmaf(yv.z, scv.z, shv.z), 0.f);
            hv.w += fmaxf(fmaf(yv.w, scv.w, shv.w), 0.f);
            *(float4*)(&g_h[(size_t)r * 128 + lane * 4]) = hv;
        }
        acc.x += hv.x; acc.y += hv.y; acc.z += hv.z; acc.w += hv.w;
    }
    sm[w][lane] = acc;
    __syncthreads();
    if (w == 0) {
        float4 t = sm[0][lane];
#pragma unroll
        for (int i = 1; i < 8; i++) {
            const float4 u = sm[i][lane];
            t.x += u.x; t.y += u.y; t.z += u.z; t.w += u.w;
        }
        *(float4*)(&pooled[(size_t)g * 128 + lane * 4]) = t;
    }
}

// ---------------- heads ----------------
__global__ void head_k(const float* __restrict__ pw, const float* __restrict__ pb,
                       float* __restrict__ out)
{
    const int g = blockIdx.x;
    const int c = threadIdx.x;
    if (c >= NC) return;
    const float cnt = (float)(g_goff[g + 1] - g_goff[g]);
    const float inv_cnt = 1.0f / fmaxf(cnt, 1.0f);
    float acc = 0.0f;
#pragma unroll
    for (int l = 0; l <= NL; l++) {
        const float* p = &g_pooled[(l * NG + g) * HID];
        float a = 0.0f;
#pragma unroll 8
        for (int f = 0; f < HID; f++)
            a = fmaf(p[f], pw[(l * HID + f) * NC + c], a);
        acc += a * inv_cnt + pb[l * NC + c];
    }
    out[g * NC + c] = acc;
}

// ---------------- launch ----------------
extern "C" void kernel_launch(void* const* d_in, const int* in_sizes, int n_in,
                              void* d_out, int out_size)
{
    const float* x     = (const float*)d_in[0];
    const int*   ei    = (const int*)d_in[1];
    const int*   batch = (const int*)d_in[2];
    const float* emb_w = (const float*)d_in[3];
    const float* emb_b = (const float*)d_in[4];
    const float* eps   = (const float*)d_in[5];
    const float* w1    = (const float*)d_in[6];
    const float* b1    = (const float*)d_in[7];
    const float* bn1g  = (const float*)d_in[8];
    const float* bn1b  = (const float*)d_in[9];
    const float* w2    = (const float*)d_in[10];
    const float* b2    = (const float*)d_in[11];
    const float* bng   = (const float*)d_in[12];
    const float* bnb   = (const float*)d_in[13];
    const float* pw    = (const float*)d_in[14];
    const float* pb    = (const float*)d_in[15];
    float*       out   = (float*)d_out;

    void *p_h, *p_agg, *p_y1, *p_y2, *p_pooled, *p_colsum, *p_colsq;
    void *p_sc1, *p_sh1, *p_sc2, *p_sh2, *p_cnt;
    cudaGetSymbolAddress(&p_h,      g_h);
    cudaGetSymbolAddress(&p_agg,    g_agg);
    cudaGetSymbolAddress(&p_y1,     g_y1);
    cudaGetSymbolAddress(&p_y2,     g_y2);
    cudaGetSymbolAddress(&p_pooled, g_pooled);
    cudaGetSymbolAddress(&p_colsum, g_colsum);
    cudaGetSymbolAddress(&p_colsq,  g_colsq);
    cudaGetSymbolAddress(&p_sc1,    g_sc1);
    cudaGetSymbolAddress(&p_sh1,    g_sh1);
    cudaGetSymbolAddress(&p_sc2,    g_sc2);
    cudaGetSymbolAddress(&p_sh2,    g_sh2);
    cudaGetSymbolAddress(&p_cnt,    g_cnt);

    cudaFuncSetAttribute(tgemm_k<0, false>, cudaFuncAttributeMaxDynamicSharedMemorySize, SM_TOT);
    cudaFuncSetAttribute(tgemm_k<0, true>,  cudaFuncAttributeMaxDynamicSharedMemorySize, SM_TOT);
    cudaFuncSetAttribute(tgemm_k<2, true>,  cudaFuncAttributeMaxDynamicSharedMemorySize, SM_TOT);

    cudaMemsetAsync(p_colsum, 0, sizeof(float) * HID);
    cudaMemsetAsync(p_colsq,  0, sizeof(float) * HID);
    cudaMemsetAsync(p_cnt,    0, sizeof(int) * NN);

    // pre-split all 9 weights in one launch: m=0 emb, m=1+2l w1[l], m=2+2l w2[l]
    wconv_k<<<dim3(16, NW), 1024>>>(emb_w, w1, w2);

    // CSR build (by dst, storing src) + graph boundaries
    hist_k<<<(NE + 255) / 256, 256>>>(ei + NE);
    scan_k<<<1, 1024>>>();
    fill_k<<<(NE + 255) / 256, 256>>>(ei, ei + NE);
    goff_k<<<(NN + 255) / 256, 256>>>(batch);

    const int GB = (NN + 127) / 128;

    // embedding
    tgemm_k<0, false><<<GB, 256, SM_TOT>>>(x, nullptr, nullptr, 0, emb_b, (float*)p_h, NN);
    pool2_k<false><<<NG, 256>>>(nullptr, nullptr, nullptr, (float*)p_pooled);

    for (int l = 0; l < NL; l++) {
        gather_k<<<(NN + 7) / 8, 256>>>(eps, l);

        tgemm_k<0, true><<<GB, 256, SM_TOT>>>((const float*)p_agg, nullptr, nullptr,
                                              1 + 2 * l, b1 + l * HID, (float*)p_y1, NN);
        bnfin_k<<<1, 128>>>(bn1g + l * HID, bn1b + l * HID, (float*)p_sc1, (float*)p_sh1);

        tgemm_k<2, true><<<GB, 256, SM_TOT>>>((const float*)p_y1, (const float*)p_sc1,
                                              (const float*)p_sh1,
                                              2 + 2 * l, b2 + l * HID, (float*)p_y2, NN);
        bnfin_k<<<1, 128>>>(bng + l * HID, bnb + l * HID, (float*)p_sc2, (float*)p_sh2);

        pool2_k<true><<<NG, 256>>>((const float*)p_y2, (const float*)p_sc2,
                                   (const float*)p_sh2,
                                   (float*)p_pooled + (size_t)(l + 1) * NG * HID);
    }

    head_k<<<NG, 32>>>(pw, pb, out);
}

// round 9
// speedup vs baseline: 1.4770x; 1.0531x over previous
#include <cuda_runtime.h>
#include <cuda_bf16.h>
#include <cstdint>

#define NN 50000
#define NE 600000
#define HID 128
#define NG 128
#define NC 10
#define NL 4
#define NW 9          // 1 emb + 2*NL layer weights
#define NPART 8       // pooling partitions per graph

// ---------------- scratch ----------------
__device__ __align__(16) float g_h[NN * HID];
__device__ __align__(16) float g_agg[NN * HID];
__device__ __align__(16) float g_y1[NN * HID];
__device__ __align__(16) float g_y2[NN * HID];
__device__ __align__(16) float g_cs[2 * NL][HID];   // BN column sums per slot
__device__ __align__(16) float g_cq[2 * NL][HID];   // BN column sumsq per slot
__device__ __align__(16) float g_pooled[(NL + 1) * NG * HID];
// CSR + graph boundaries
__device__ int g_cnt[NN];
__device__ int g_rowptr[NN + 1];
__device__ int g_cursor[NN];
__device__ int g_csr[NE];
__device__ int g_goff[NG + 1];
// pre-split weights, transposed [n][k], bf16 hi/lo
__device__ __align__(16) __nv_bfloat16 g_whi[NW * HID * HID];
__device__ __align__(16) __nv_bfloat16 g_wlo[NW * HID * HID];

// ---------------- helpers ----------------
__device__ __forceinline__ uint32_t smem_u32(const void* p) {
    uint32_t a;
    asm("{ .reg .u64 t; cvta.to.shared.u64 t, %1; cvt.u32.u64 %0, t; }" : "=r"(a) : "l"(p));
    return a;
}
__device__ __forceinline__ void ldsm4(uint32_t* r, uint32_t addr) {
    asm volatile("ldmatrix.sync.aligned.m8n8.x4.shared.b16 {%0,%1,%2,%3}, [%4];"
                 : "=r"(r[0]), "=r"(r[1]), "=r"(r[2]), "=r"(r[3]) : "r"(addr));
}
__device__ __forceinline__ void mma16816(float* c, const uint32_t* a, const uint32_t* b) {
    asm volatile(
        "mma.sync.aligned.m16n8k16.row.col.f32.bf16.bf16.f32 "
        "{%0,%1,%2,%3}, {%4,%5,%6,%7}, {%8,%9}, {%0,%1,%2,%3};"
        : "+f"(c[0]), "+f"(c[1]), "+f"(c[2]), "+f"(c[3])
        : "r"(a[0]), "r"(a[1]), "r"(a[2]), "r"(a[3]), "r"(b[0]), "r"(b[1]));
}

// tile leading dim: 128+8 -> 272B rows, conflict-free LDSM
#define LDT 136
#define A_TILE_B (64 * LDT * 2)     // 17408
#define B_TILE_B (128 * LDT * 2)    // 34816
#define SM_TOT (2 * A_TILE_B + 2 * B_TILE_B)   // 104448

// ---------------- weight pre-split (all 9 matrices in one launch) ----------------
__global__ void wconv_k(const float* __restrict__ emb_w,
                        const float* __restrict__ w1,
                        const float* __restrict__ w2)
{
    const int m = blockIdx.y;
    const float* W = (m == 0) ? emb_w
                   : ((m & 1) ? w1 + (size_t)((m - 1) >> 1) * HID * HID
                              : w2 + (size_t)((m >> 1) - 1) * HID * HID);
    const int o = blockIdx.x * 1024 + threadIdx.x;
    if (o >= HID * HID) return;
    const int n = o >> 7, k = o & 127;
    const float w = __ldg(&W[k * 128 + n]);
    const __nv_bfloat16 h = __float2bfloat16(w);
    g_whi[(size_t)m * HID * HID + o] = h;
    g_wlo[(size_t)m * HID * HID + o] = __float2bfloat16(w - __bfloat162float(h));
}

// ---------------- tensor GEMM: out[64-row tile,128] = f(A) @ W + bias ----------------
// MODE 0: a = A
// MODE 2: a = relu(A*sc + sh), sc/sh computed from stats slot sIn + gam/bet
// STATS: accumulate column sum/sumsq of output into slot sOut.
template <int MODE, bool STATS>
__global__ void __launch_bounds__(256) tgemm_k(
    const float* __restrict__ A,
    const float* __restrict__ gam, const float* __restrict__ bet, int sIn,
    int sOut, int widx, const float* __restrict__ bias,
    float* __restrict__ out, int n)
{
    extern __shared__ char smem[];
    __nv_bfloat16* Ahi = (__nv_bfloat16*)(smem);
    __nv_bfloat16* Alo = (__nv_bfloat16*)(smem + A_TILE_B);
    __nv_bfloat16* Bhi = (__nv_bfloat16*)(smem + 2 * A_TILE_B);
    __nv_bfloat16* Blo = (__nv_bfloat16*)(smem + 2 * A_TILE_B + B_TILE_B);
    __shared__ float s_sum[128], s_sq[128];
    __shared__ float s_sc[128], s_sh[128];

    const int tid = threadIdx.x;
    const int lane = tid & 31;
    const int wid = tid >> 5;
    const int wm = wid & 1;       // 2 warps along M (32 rows each)
    const int wn = wid >> 1;      // 4 warps along N (32 cols each)
    const int row0 = blockIdx.x * 64;

    if (STATS && tid < 128) { s_sum[tid] = 0.f; s_sq[tid] = 0.f; }
    if (MODE == 2) {
        if (tid < 128) {
            const float inv_n = 1.0f / (float)NN;
            const float m = g_cs[sIn][tid] * inv_n;
            const float var = g_cq[sIn][tid] * inv_n - m * m;
            const float s = gam[tid] * rsqrtf(var + 1e-5f);
            s_sc[tid] = s;
            s_sh[tid] = bet[tid] - m * s;
        }
        __syncthreads();
    }

    // ---- A tile: thread owns row tid/4, 32-col quarter ----
    {
        const int r = tid >> 2;
        const int row = row0 + r;
        const int cb = (tid & 3) * 32;
        const float4* Ar = (const float4*)(A + (size_t)row * 128 + cb);
#pragma unroll
        for (int i = 0; i < 4; i++) {
            float v[8] = {0, 0, 0, 0, 0, 0, 0, 0};
            if (row < n) {
                float4 a0 = Ar[2 * i], a1 = Ar[2 * i + 1];
                v[0] = a0.x; v[1] = a0.y; v[2] = a0.z; v[3] = a0.w;
                v[4] = a1.x; v[5] = a1.y; v[6] = a1.z; v[7] = a1.w;
                if (MODE == 2) {
#pragma unroll
                    for (int u = 0; u < 8; u++)
                        v[u] = fmaxf(fmaf(v[u], s_sc[cb + i * 8 + u], s_sh[cb + i * 8 + u]), 0.f);
                }
            }
            __nv_bfloat16 hi[8], lo[8];
#pragma unroll
            for (int u = 0; u < 8; u++) {
                hi[u] = __float2bfloat16(v[u]);
                lo[u] = __float2bfloat16(v[u] - __bfloat162float(hi[u]));
            }
            const int base = r * LDT + cb + i * 8;
            *(float4*)&Ahi[base] = *(const float4*)hi;
            *(float4*)&Alo[base] = *(const float4*)lo;
        }
    }
    // ---- B tile: pure copy from pre-split transposed weights ----
    {
        const int r = tid >> 1;
        const int kc = (tid & 1) * 64;
        const float4* sh4 = (const float4*)(g_whi + (size_t)widx * HID * HID + r * 128 + kc);
        const float4* sl4 = (const float4*)(g_wlo + (size_t)widx * HID * HID + r * 128 + kc);
#pragma unroll
        for (int i = 0; i < 8; i++) {
            const int base = r * LDT + kc + i * 8;
            *(float4*)&Bhi[base] = sh4[i];
            *(float4*)&Blo[base] = sl4[i];
        }
    }
    __syncthreads();

    // ---- warp mma mainloop: 32x32 per warp ----
    float acc[2][4][4];
#pragma unroll
    for (int mt = 0; mt < 2; mt++)
#pragma unroll
        for (int j = 0; j < 4; j++)
#pragma unroll
            for (int u = 0; u < 4; u++) acc[mt][j][u] = 0.f;

    const uint32_t sAhi = smem_u32(Ahi), sAlo = smem_u32(Alo);
    const uint32_t sBhi = smem_u32(Bhi), sBlo = smem_u32(Blo);

    const int aRow = wm * 32 + (lane & 15);
    const int aCol = (lane >> 4) * 8;
    const int bR = wn * 32 + (lane & 7) + ((lane >> 3) & 1) * 8;
    const int bC = (lane >> 4) * 8;

#pragma unroll
    for (int ks = 0; ks < 8; ks++) {
        uint32_t ahi[2][4], alo[2][4], bhi[4][2], blo[4][2];
        const int kc = ks * 16;
#pragma unroll
        for (int mt = 0; mt < 2; mt++) {
            const uint32_t off = ((aRow + mt * 16) * LDT + kc + aCol) * 2;
            ldsm4(ahi[mt], sAhi + off);
            ldsm4(alo[mt], sAlo + off);
        }
#pragma unroll
        for (int jp = 0; jp < 2; jp++) {
            const uint32_t off = ((bR + jp * 16) * LDT + kc + bC) * 2;
            uint32_t th[4], tl[4];
            ldsm4(th, sBhi + off);
            ldsm4(tl, sBlo + off);
            bhi[2 * jp][0] = th[0];     bhi[2 * jp][1] = th[2];
            bhi[2 * jp + 1][0] = th[1]; bhi[2 * jp + 1][1] = th[3];
            blo[2 * jp][0] = tl[0];     blo[2 * jp][1] = tl[2];
            blo[2 * jp + 1][0] = tl[1]; blo[2 * jp + 1][1] = tl[3];
        }
#pragma unroll
        for (int mt = 0; mt < 2; mt++)
#pragma unroll
            for (int j = 0; j < 4; j++) {
                mma16816(acc[mt][j], ahi[mt], bhi[j]);
                mma16816(acc[mt][j], ahi[mt], blo[j]);
                mma16816(acc[mt][j], alo[mt], bhi[j]);
            }
    }

    // ---- epilogue: bias + store (+ fused column stats) ----
    float st[4][4];
    if (STATS) {
#pragma unroll
        for (int j = 0; j < 4; j++)
#pragma unroll
            for (int u = 0; u < 4; u++) st[j][u] = 0.f;
    }
#pragma unroll
    for (int mt = 0; mt < 2; mt++) {
        const int r_lo = row0 + wm * 32 + mt * 16 + (lane >> 2);
        const int r_hi = r_lo + 8;
#pragma unroll
        for (int j = 0; j < 4; j++) {
            const int c = wn * 32 + j * 8 + (lane & 3) * 2;
            const float b0 = bias[c], b1 = bias[c + 1];
            if (r_lo < n) {
                const float v0 = acc[mt][j][0] + b0, v1 = acc[mt][j][1] + b1;
                *(float2*)(out + (size_t)r_lo * 128 + c) = make_float2(v0, v1);
                if (STATS) {
                    st[j][0] += v0; st[j][1] += v1;
                    st[j][2] = fmaf(v0, v0, st[j][2]); st[j][3] = fmaf(v1, v1, st[j][3]);
                }
            }
            if (r_hi < n) {
                const float v0 = acc[mt][j][2] + b0, v1 = acc[mt][j][3] + b1;
                *(float2*)(out + (size_t)r_hi * 128 + c) = make_float2(v0, v1);
                if (STATS) {
                    st[j][0] += v0; st[j][1] += v1;
                    st[j][2] = fmaf(v0, v0, st[j][2]); st[j][3] = fmaf(v1, v1, st[j][3]);
                }
            }
        }
    }
    if (STATS) {
#pragma unroll
        for (int j = 0; j < 4; j++)
#pragma unroll
            for (int u = 0; u < 4; u++) {
                st[j][u] += __shfl_xor_sync(0xFFFFFFFF, st[j][u], 4);
                st[j][u] += __shfl_xor_sync(0xFFFFFFFF, st[j][u], 8);
                st[j][u] += __shfl_xor_sync(0xFFFFFFFF, st[j][u], 16);
            }
        if (lane < 4) {
#pragma unroll
            for (int j = 0; j < 4; j++) {
                const int c = wn * 32 + j * 8 + lane * 2;
                atomicAdd(&s_sum[c], st[j][0]);
                atomicAdd(&s_sum[c + 1], st[j][1]);
                atomicAdd(&s_sq[c], st[j][2]);
                atomicAdd(&s_sq[c + 1], st[j][3]);
            }
        }
        __syncthreads();
        if (tid < 128) {
            atomicAdd(&g_cs[sOut][tid], s_sum[tid]);
            atomicAdd(&g_cq[sOut][tid], s_sq[tid]);
        }
    }
}

// ---------------- CSR build ----------------
__global__ void hist_k(const int* __restrict__ dst)
{
    const int e = blockIdx.x * 256 + threadIdx.x;
    if (e < NE) atomicAdd(&g_cnt[dst[e]], 1);
}

__global__ void __launch_bounds__(1024) scan_k()
{
    __shared__ int sm[1024];
    const int t = threadIdx.x;
    const int per = (NN + 1023) / 1024;
    const int beg = t * per;
    const int end = min(beg + per, NN);
    int s = 0;
    for (int i = beg; i < end; i++) s += g_cnt[i];
    sm[t] = s;
    __syncthreads();
    for (int off = 1; off < 1024; off <<= 1) {
        int v = (t >= off) ? sm[t - off] : 0;
        __syncthreads();
        sm[t] += v;
        __syncthreads();
    }
    int run = sm[t] - s;   // exclusive prefix
    for (int i = beg; i < end; i++) {
        const int c = g_cnt[i];
        g_rowptr[i] = run;
        g_cursor[i] = run;
        run += c;
    }
    if (t == 1023) g_rowptr[NN] = sm[1023];
}

__global__ void fill_k(const int* __restrict__ src, const int* __restrict__ dst)
{
    const int e = blockIdx.x * 256 + threadIdx.x;
    if (e >= NE) return;
    const int pos = atomicAdd(&g_cursor[dst[e]], 1);
    g_csr[pos] = src[e];
}

// ---------------- graph boundaries from sorted batch ----------------
__global__ void goff_k(const int* __restrict__ batch)
{
    const int i = blockIdx.x * 256 + threadIdx.x;
    if (i >= NN) return;
    const int b = batch[i];
    if (i == 0) {
        for (int g = 0; g <= b; g++) g_goff[g] = 0;
    } else {
        const int pb = batch[i - 1];
        for (int g = pb + 1; g <= b; g++) g_goff[g] = i;
    }
    if (i == NN - 1) {
        for (int g = b + 1; g <= NG; g++) g_goff[g] = NN;
    }
}

// ---------------- gather: agg[v] = (1+eps)*h[v] + sum_{u->v} h[u] (MLP-4) ----------------
__global__ void __launch_bounds__(256) gather_k(const float* __restrict__ epsPtr, int layer)
{
    const int node = blockIdx.x * 8 + (threadIdx.x >> 5);
    if (node >= NN) return;
    const int lane = threadIdx.x & 31;
    const float oe = 1.0f + epsPtr[layer];
    const float4 hv = *(const float4*)(&g_h[(size_t)node * 128 + lane * 4]);
    float4 acc = make_float4(oe * hv.x, oe * hv.y, oe * hv.z, oe * hv.w);
    const int rp0 = g_rowptr[node], rp1 = g_rowptr[node + 1];
    int e = rp0;
    for (; e + 3 < rp1; e += 4) {
        const int s0 = g_csr[e], s1 = g_csr[e + 1], s2 = g_csr[e + 2], s3 = g_csr[e + 3];
        const float4 v0 = *(const float4*)(&g_h[(size_t)s0 * 128 + lane * 4]);
        const float4 v1 = *(const float4*)(&g_h[(size_t)s1 * 128 + lane * 4]);
        const float4 v2 = *(const float4*)(&g_h[(size_t)s2 * 128 + lane * 4]);
        const float4 v3 = *(const float4*)(&g_h[(size_t)s3 * 128 + lane * 4]);
        acc.x += v0.x + v1.x + v2.x + v3.x;
        acc.y += v0.y + v1.y + v2.y + v3.y;
        acc.z += v0.z + v1.z + v2.z + v3.z;
        acc.w += v0.w + v1.w + v2.w + v3.w;
    }
    for (; e < rp1; e++) {
        const int s = g_csr[e];
        const float4 v = *(const float4*)(&g_h[(size_t)s * 128 + lane * 4]);
        acc.x += v.x; acc.y += v.y; acc.z += v.z; acc.w += v.w;
    }
    *(float4*)(&g_agg[(size_t)node * 128 + lane * 4]) = acc;
}

// ---------------- partitioned pooling: grid (NG, NPART) ----------------
// UPDATE: h += relu(y2*sc+sh) first (sc/sh from stats slot sIn + gam/bet),
// then pooled[g] += partial sum of h over this partition's rows.
template <bool UPDATE>
__global__ void __launch_bounds__(256) pool2_k(const float* __restrict__ y2,
                                               const float* __restrict__ gam,
                                               const float* __restrict__ bet, int sIn,
                                               float* __restrict__ pooled)
{
    __shared__ float4 sm[8][32];
    __shared__ float s_sc[128], s_sh[128];
    const int g = blockIdx.x, part = blockIdx.y;
    const int lane = threadIdx.x & 31;
    const int w = threadIdx.x >> 5;

    if (UPDATE) {
        if (threadIdx.x < 128) {
            const float inv_n = 1.0f / (float)NN;
            const float m = g_cs[sIn][threadIdx.x] * inv_n;
            const float var = g_cq[sIn][threadIdx.x] * inv_n - m * m;
            const float s = gam[threadIdx.x] * rsqrtf(var + 1e-5f);
            s_sc[threadIdx.x] = s;
            s_sh[threadIdx.x] = bet[threadIdx.x] - m * s;
        }
        __syncthreads();
    }
    const int beg = g_goff[g], end = g_goff[g + 1];

    float4 scv, shv;
    if (UPDATE) {
        scv = *(const float4*)(&s_sc[lane * 4]);
        shv = *(const float4*)(&s_sh[lane * 4]);
    }
    float4 acc = make_float4(0.f, 0.f, 0.f, 0.f);
    for (int r = beg + part * 8 + w; r < end; r += NPART * 8) {
        float4 hv = *(const float4*)(&g_h[(size_t)r * 128 + lane * 4]);
        if (UPDATE) {
            const float4 yv = *(const float4*)(&y2[(size_t)r * 128 + lane * 4]);
            hv.x += fmaxf(fmaf(yv.x, scv.x, shv.x), 0.f);
            hv.y += fmaxf(fmaf(yv.y, scv.y, shv.y), 0.f);
            hv.z += fmaxf(fmaf(yv.z, scv.z, shv.z), 0.f);
            hv.w += fmaxf(fmaf(yv.w, scv.w, shv.w), 0.f);
            *(float4*)(&g_h[(size_t)r * 128 + lane * 4]) = hv;
        }
        acc.x += hv.x; acc.y += hv.y; acc.z += hv.z; acc.w += hv.w;
    }
    sm[w][lane] = acc;
    __syncthreads();
    if (w == 0) {
        float4 t = sm[0][lane];
#pragma unroll
        for (int i = 1; i < 8; i++) {
            const float4 u = sm[i][lane];
            t.x += u.x; t.y += u.y; t.z += u.z; t.w += u.w;
        }
        atomicAdd((float4*)(&pooled[(size_t)g * 128 + lane * 4]), t);
    }
}

// ---------------- heads ----------------
__global__ void head_k(const float* __restrict__ pw, const float* __restrict__ pb,
                       float* __restrict__ out)
{
    const int g = blockIdx.x;
    const int c = threadIdx.x;
    if (c >= NC) return;
    const float cnt = (float)(g_goff[g + 1] - g_goff[g]);
    const float inv_cnt = 1.0f / fmaxf(cnt, 1.0f);
    float acc = 0.0f;
#pragma unroll
    for (int l = 0; l <= NL; l++) {
        const float* p = &g_pooled[(l * NG + g) * HID];
        float a = 0.0f;
#pragma unroll 8
        for (int f = 0; f < HID; f++)
            a = fmaf(p[f], pw[(l * HID + f) * NC + c], a);
        acc += a * inv_cnt + pb[l * NC + c];
    }
    out[g * NC + c] = acc;
}

// ---------------- launch ----------------
extern "C" void kernel_launch(void* const* d_in, const int* in_sizes, int n_in,
                              void* d_out, int out_size)
{
    const float* x     = (const float*)d_in[0];
    const int*   ei    = (const int*)d_in[1];
    const int*   batch = (const int*)d_in[2];
    const float* emb_w = (const float*)d_in[3];
    const float* emb_b = (const float*)d_in[4];
    const float* eps   = (const float*)d_in[5];
    const float* w1    = (const float*)d_in[6];
    const float* b1    = (const float*)d_in[7];
    const float* bn1g  = (const float*)d_in[8];
    const float* bn1b  = (const float*)d_in[9];
    const float* w2    = (const float*)d_in[10];
    const float* b2    = (const float*)d_in[11];
    const float* bng   = (const float*)d_in[12];
    const float* bnb   = (const float*)d_in[13];
    const float* pw    = (const float*)d_in[14];
    const float* pb    = (const float*)d_in[15];
    float*       out   = (float*)d_out;

    void *p_h, *p_agg, *p_y1, *p_y2, *p_pooled, *p_cs, *p_cq, *p_cnt;
    cudaGetSymbolAddress(&p_h,      g_h);
    cudaGetSymbolAddress(&p_agg,    g_agg);
    cudaGetSymbolAddress(&p_y1,     g_y1);
    cudaGetSymbolAddress(&p_y2,     g_y2);
    cudaGetSymbolAddress(&p_pooled, g_pooled);
    cudaGetSymbolAddress(&p_cs,     g_cs);
    cudaGetSymbolAddress(&p_cq,     g_cq);
    cudaGetSymbolAddress(&p_cnt,    g_cnt);

    cudaFuncSetAttribute(tgemm_k<0, false>, cudaFuncAttributeMaxDynamicSharedMemorySize, SM_TOT);
    cudaFuncSetAttribute(tgemm_k<0, true>,  cudaFuncAttributeMaxDynamicSharedMemorySize, SM_TOT);
    cudaFuncSetAttribute(tgemm_k<2, true>,  cudaFuncAttributeMaxDynamicSharedMemorySize, SM_TOT);

    cudaMemsetAsync(p_cs,     0, sizeof(float) * 2 * NL * HID);
    cudaMemsetAsync(p_cq,     0, sizeof(float) * 2 * NL * HID);
    cudaMemsetAsync(p_pooled, 0, sizeof(float) * (NL + 1) * NG * HID);
    cudaMemsetAsync(p_cnt,    0, sizeof(int) * NN);

    // pre-split all 9 weights: m=0 emb, m=1+2l w1[l], m=2+2l w2[l]
    wconv_k<<<dim3(16, NW), 1024>>>(emb_w, w1, w2);

    // CSR build (by dst, storing src) + graph boundaries
    hist_k<<<(NE + 255) / 256, 256>>>(ei + NE);
    scan_k<<<1, 1024>>>();
    fill_k<<<(NE + 255) / 256, 256>>>(ei, ei + NE);
    goff_k<<<(NN + 255) / 256, 256>>>(batch);

    const int GB = (NN + 63) / 64;

    // embedding
    tgemm_k<0, false><<<GB, 256, SM_TOT>>>(x, nullptr, nullptr, 0,
                                           0, 0, emb_b, (float*)p_h, NN);
    pool2_k<false><<<dim3(NG, NPART), 256>>>(nullptr, nullptr, nullptr, 0, (float*)p_pooled);

    for (int l = 0; l < NL; l++) {
        gather_k<<<(NN + 7) / 8, 256>>>(eps, l);

        // y1 = agg @ w1 + b1, stats -> slot 2l
        tgemm_k<0, true><<<GB, 256, SM_TOT>>>((const float*)p_agg, nullptr, nullptr, 0,
                                              2 * l, 1 + 2 * l, b1 + l * HID,
                                              (float*)p_y1, NN);
        // y2 = relu(bn1(y1)) @ w2 + b2, bn from slot 2l, stats -> slot 2l+1
        tgemm_k<2, true><<<GB, 256, SM_TOT>>>((const float*)p_y1,
                                              bn1g + l * HID, bn1b + l * HID, 2 * l,
                                              2 * l + 1, 2 + 2 * l, b2 + l * HID,
                                              (float*)p_y2, NN);
        // h += relu(bn2(y2)); pool hidden[l+1]; bn from slot 2l+1
        pool2_k<true><<<dim3(NG, NPART), 256>>>((const float*)p_y2,
                                                bng + l * HID, bnb + l * HID, 2 * l + 1,
                                                (float*)p_pooled + (size_t)(l + 1) * NG * HID);
    }

    head_k<<<NG, 32>>>(pw, pb, out);
}

// round 10
// speedup vs baseline: 1.4774x; 1.0003x over previous
#include <cuda_runtime.h>
#include <cuda_bf16.h>
#include <cstdint>

#define NN 50000
#define NE 600000
#define HID 128
#define NG 128
#define NC 10
#define NL 4
#define NW 9          // 1 emb + 2*NL layer weights
#define NPART 8       // pooling partitions per graph

// ---------------- scratch ----------------
__device__ __align__(16) float g_h[NN * HID];
__device__ __align__(16) float g_agg[NN * HID];
__device__ __align__(16) float g_y1[NN * HID];
__device__ __align__(16) float g_y2[NN * HID];
__device__ __align__(16) float g_cs[2 * NL][HID];   // BN column sums per slot
__device__ __align__(16) float g_cq[2 * NL][HID];   // BN column sumsq per slot
__device__ __align__(16) float g_pooled[(NL + 1) * NG * HID];
// CSR + graph boundaries
__device__ int g_cnt[NN];
__device__ int g_rowptr[NN + 1];
__device__ int g_cursor[NN];
__device__ int g_csr[NE];
__device__ int g_goff[NG + 1];
// pre-split weights, transposed [n][k], bf16 hi/lo
__device__ __align__(16) __nv_bfloat16 g_whi[NW * HID * HID];
__device__ __align__(16) __nv_bfloat16 g_wlo[NW * HID * HID];

// ---------------- helpers ----------------
__device__ __forceinline__ uint32_t smem_u32(const void* p) {
    uint32_t a;
    asm("{ .reg .u64 t; cvta.to.shared.u64 t, %1; cvt.u32.u64 %0, t; }" : "=r"(a) : "l"(p));
    return a;
}
__device__ __forceinline__ void ldsm4(uint32_t* r, uint32_t addr) {
    asm volatile("ldmatrix.sync.aligned.m8n8.x4.shared.b16 {%0,%1,%2,%3}, [%4];"
                 : "=r"(r[0]), "=r"(r[1]), "=r"(r[2]), "=r"(r[3]) : "r"(addr));
}
__device__ __forceinline__ void mma16816(float* c, const uint32_t* a, const uint32_t* b) {
    asm volatile(
        "mma.sync.aligned.m16n8k16.row.col.f32.bf16.bf16.f32 "
        "{%0,%1,%2,%3}, {%4,%5,%6,%7}, {%8,%9}, {%0,%1,%2,%3};"
        : "+f"(c[0]), "+f"(c[1]), "+f"(c[2]), "+f"(c[3])
        : "r"(a[0]), "r"(a[1]), "r"(a[2]), "r"(a[3]), "r"(b[0]), "r"(b[1]));
}

// tile leading dim: 128+8 -> 272B rows, conflict-free LDSM
#define LDT 136
#define A_TILE_B (64 * LDT * 2)     // 17408
#define B_TILE_B (128 * LDT * 2)    // 34816
#define SM_TOT (2 * A_TILE_B + 2 * B_TILE_B)   // 104448

// ---------------- weight pre-split (all 9 matrices in one launch) ----------------
__global__ void wconv_k(const float* __restrict__ emb_w,
                        const float* __restrict__ w1,
                        const float* __restrict__ w2)
{
    const int m = blockIdx.y;
    const float* W = (m == 0) ? emb_w
                   : ((m & 1) ? w1 + (size_t)((m - 1) >> 1) * HID * HID
                              : w2 + (size_t)((m >> 1) - 1) * HID * HID);
    const int o = blockIdx.x * 1024 + threadIdx.x;
    if (o >= HID * HID) return;
    const int n = o >> 7, k = o & 127;
    const float w = __ldg(&W[k * 128 + n]);
    const __nv_bfloat16 h = __float2bfloat16(w);
    g_whi[(size_t)m * HID * HID + o] = h;
    g_wlo[(size_t)m * HID * HID + o] = __float2bfloat16(w - __bfloat162float(h));
}

// ---------------- tensor GEMM: out[64-row tile,128] = f(A) @ W + bias ----------------
// MODE 0: a = A
// MODE 2: a = relu(A*sc + sh), sc/sh computed from stats slot sIn + gam/bet
// STATS: accumulate column sum/sumsq of output into slot sOut.
template <int MODE, bool STATS>
__global__ void __launch_bounds__(256) tgemm_k(
    const float* __restrict__ A,
    const float* __restrict__ gam, const float* __restrict__ bet, int sIn,
    int sOut, int widx, const float* __restrict__ bias,
    float* __restrict__ out, int n)
{
    extern __shared__ char smem[];
    __nv_bfloat16* Ahi = (__nv_bfloat16*)(smem);
    __nv_bfloat16* Alo = (__nv_bfloat16*)(smem + A_TILE_B);
    __nv_bfloat16* Bhi = (__nv_bfloat16*)(smem + 2 * A_TILE_B);
    __nv_bfloat16* Blo = (__nv_bfloat16*)(smem + 2 * A_TILE_B + B_TILE_B);
    __shared__ float s_sum[128], s_sq[128];
    __shared__ float s_sc[128], s_sh[128];

    const int tid = threadIdx.x;
    const int lane = tid & 31;
    const int wid = tid >> 5;
    const int wm = wid & 1;       // 2 warps along M (32 rows each)
    const int wn = wid >> 1;      // 4 warps along N (32 cols each)
    const int row0 = blockIdx.x * 64;

    if (STATS && tid < 128) { s_sum[tid] = 0.f; s_sq[tid] = 0.f; }
    if (MODE == 2) {
        if (tid < 128) {
            const float inv_n = 1.0f / (float)NN;
            const float m = g_cs[sIn][tid] * inv_n;
            const float var = g_cq[sIn][tid] * inv_n - m * m;
            const float s = gam[tid] * rsqrtf(var + 1e-5f);
            s_sc[tid] = s;
            s_sh[tid] = bet[tid] - m * s;
        }
        __syncthreads();
    }

    // ---- A tile: thread owns row tid/4, 32-col quarter ----
    {
        const int r = tid >> 2;
        const int row = row0 + r;
        const int cb = (tid & 3) * 32;
        const float4* Ar = (const float4*)(A + (size_t)row * 128 + cb);
#pragma unroll
        for (int i = 0; i < 4; i++) {
            float v[8] = {0, 0, 0, 0, 0, 0, 0, 0};
            if (row < n) {
                float4 a0 = Ar[2 * i], a1 = Ar[2 * i + 1];
                v[0] = a0.x; v[1] = a0.y; v[2] = a0.z; v[3] = a0.w;
                v[4] = a1.x; v[5] = a1.y; v[6] = a1.z; v[7] = a1.w;
                if (MODE == 2) {
#pragma unroll
                    for (int u = 0; u < 8; u++)
                        v[u] = fmaxf(fmaf(v[u], s_sc[cb + i * 8 + u], s_sh[cb + i * 8 + u]), 0.f);
                }
            }
            __nv_bfloat16 hi[8], lo[8];
#pragma unroll
            for (int u = 0; u < 8; u++) {
                hi[u] = __float2bfloat16(v[u]);
                lo[u] = __float2bfloat16(v[u] - __bfloat162float(hi[u]));
            }
            const int base = r * LDT + cb + i * 8;
            *(float4*)&Ahi[base] = *(const float4*)hi;
            *(float4*)&Alo[base] = *(const float4*)lo;
        }
    }
    // ---- B tile: pure copy from pre-split transposed weights ----
    {
        const int r = tid >> 1;
        const int kc = (tid & 1) * 64;
        const float4* sh4 = (const float4*)(g_whi + (size_t)widx * HID * HID + r * 128 + kc);
        const float4* sl4 = (const float4*)(g_wlo + (size_t)widx * HID * HID + r * 128 + kc);
#pragma unroll
        for (int i = 0; i < 8; i++) {
            const int base = r * LDT + kc + i * 8;
            *(float4*)&Bhi[base] = sh4[i];
            *(float4*)&Blo[base] = sl4[i];
        }
    }
    __syncthreads();

    // ---- warp mma mainloop: 32x32 per warp ----
    float acc[2][4][4];
#pragma unroll
    for (int mt = 0; mt < 2; mt++)
#pragma unroll
        for (int j = 0; j < 4; j++)
#pragma unroll
            for (int u = 0; u < 4; u++) acc[mt][j][u] = 0.f;

    const uint32_t sAhi = smem_u32(Ahi), sAlo = smem_u32(Alo);
    const uint32_t sBhi = smem_u32(Bhi), sBlo = smem_u32(Blo);

    const int aRow = wm * 32 + (lane & 15);
    const int aCol = (lane >> 4) * 8;
    const int bR = wn * 32 + (lane & 7) + ((lane >> 3) & 1) * 8;
    const int bC = (lane >> 4) * 8;

#pragma unroll
    for (int ks = 0; ks < 8; ks++) {
        uint32_t ahi[2][4], alo[2][4], bhi[4][2], blo[4][2];
        const int kc = ks * 16;
#pragma unroll
        for (int mt = 0; mt < 2; mt++) {
            const uint32_t off = ((aRow + mt * 16) * LDT + kc + aCol) * 2;
            ldsm4(ahi[mt], sAhi + off);
            ldsm4(alo[mt], sAlo + off);
        }
#pragma unroll
        for (int jp = 0; jp < 2; jp++) {
            const uint32_t off = ((bR + jp * 16) * LDT + kc + bC) * 2;
            uint32_t th[4], tl[4];
            ldsm4(th, sBhi + off);
            ldsm4(tl, sBlo + off);
            bhi[2 * jp][0] = th[0];     bhi[2 * jp][1] = th[2];
            bhi[2 * jp + 1][0] = th[1]; bhi[2 * jp + 1][1] = th[3];
            blo[2 * jp][0] = tl[0];     blo[2 * jp][1] = tl[2];
            blo[2 * jp + 1][0] = tl[1]; blo[2 * jp + 1][1] = tl[3];
        }
#pragma unroll
        for (int mt = 0; mt < 2; mt++)
#pragma unroll
            for (int j = 0; j < 4; j++) {
                mma16816(acc[mt][j], ahi[mt], bhi[j]);
                mma16816(acc[mt][j], ahi[mt], blo[j]);
                mma16816(acc[mt][j], alo[mt], bhi[j]);
            }
    }

    // ---- epilogue: bias + store (+ fused column stats) ----
    float st[4][4];
    if (STATS) {
#pragma unroll
        for (int j = 0; j < 4; j++)
#pragma unroll
            for (int u = 0; u < 4; u++) st[j][u] = 0.f;
    }
#pragma unroll
    for (int mt = 0; mt < 2; mt++) {
        const int r_lo = row0 + wm * 32 + mt * 16 + (lane >> 2);
        const int r_hi = r_lo + 8;
#pragma unroll
        for (int j = 0; j < 4; j++) {
            const int c = wn * 32 + j * 8 + (lane & 3) * 2;
            const float b0 = bias[c], b1 = bias[c + 1];
            if (r_lo < n) {
                const float v0 = acc[mt][j][0] + b0, v1 = acc[mt][j][1] + b1;
                *(float2*)(out + (size_t)r_lo * 128 + c) = make_float2(v0, v1);
                if (STATS) {
                    st[j][0] += v0; st[j][1] += v1;
                    st[j][2] = fmaf(v0, v0, st[j][2]); st[j][3] = fmaf(v1, v1, st[j][3]);
                }
            }
            if (r_hi < n) {
                const float v0 = acc[mt][j][2] + b0, v1 = acc[mt][j][3] + b1;
                *(float2*)(out + (size_t)r_hi * 128 + c) = make_float2(v0, v1);
                if (STATS) {
                    st[j][0] += v0; st[j][1] += v1;
                    st[j][2] = fmaf(v0, v0, st[j][2]); st[j][3] = fmaf(v1, v1, st[j][3]);
                }
            }
        }
    }
    if (STATS) {
#pragma unroll
        for (int j = 0; j < 4; j++)
#pragma unroll
            for (int u = 0; u < 4; u++) {
                st[j][u] += __shfl_xor_sync(0xFFFFFFFF, st[j][u], 4);
                st[j][u] += __shfl_xor_sync(0xFFFFFFFF, st[j][u], 8);
                st[j][u] += __shfl_xor_sync(0xFFFFFFFF, st[j][u], 16);
            }
        if (lane < 4) {
#pragma unroll
            for (int j = 0; j < 4; j++) {
                const int c = wn * 32 + j * 8 + lane * 2;
                atomicAdd(&s_sum[c], st[j][0]);
                atomicAdd(&s_sum[c + 1], st[j][1]);
                atomicAdd(&s_sq[c], st[j][2]);
                atomicAdd(&s_sq[c + 1], st[j][3]);
            }
        }
        __syncthreads();
        if (tid < 128) {
            atomicAdd(&g_cs[sOut][tid], s_sum[tid]);
            atomicAdd(&g_cq[sOut][tid], s_sq[tid]);
        }
    }
}

// ---------------- CSR build ----------------
__global__ void hist_k(const int* __restrict__ dst)
{
    const int e = blockIdx.x * 256 + threadIdx.x;
    if (e < NE) atomicAdd(&g_cnt[dst[e]], 1);
}

__global__ void __launch_bounds__(1024) scan_k()
{
    __shared__ int sm[1024];
    const int t = threadIdx.x;
    const int per = (NN + 1023) / 1024;
    const int beg = t * per;
    const int end = min(beg + per, NN);
    int s = 0;
    for (int i = beg; i < end; i++) s += g_cnt[i];
    sm[t] = s;
    __syncthreads();
    for (int off = 1; off < 1024; off <<= 1) {
        int v = (t >= off) ? sm[t - off] : 0;
        __syncthreads();
        sm[t] += v;
        __syncthreads();
    }
    int run = sm[t] - s;   // exclusive prefix
    for (int i = beg; i < end; i++) {
        const int c = g_cnt[i];
        g_rowptr[i] = run;
        g_cursor[i] = run;
        run += c;
    }
    if (t == 1023) g_rowptr[NN] = sm[1023];
}

__global__ void fill_k(const int* __restrict__ src, const int* __restrict__ dst)
{
    const int e = blockIdx.x * 256 + threadIdx.x;
    if (e >= NE) return;
    const int pos = atomicAdd(&g_cursor[dst[e]], 1);
    g_csr[pos] = src[e];
}

// ---------------- graph boundaries from sorted batch ----------------
__global__ void goff_k(const int* __restrict__ batch)
{
    const int i = blockIdx.x * 256 + threadIdx.x;
    if (i >= NN) return;
    const int b = batch[i];
    if (i == 0) {
        for (int g = 0; g <= b; g++) g_goff[g] = 0;
    } else {
        const int pb = batch[i - 1];
        for (int g = pb + 1; g <= b; g++) g_goff[g] = i;
    }
    if (i == NN - 1) {
        for (int g = b + 1; g <= NG; g++) g_goff[g] = NN;
    }
}

// ---------------- gather: agg[v] = (1+eps)*h[v] + sum_{u->v} h[u] (MLP-4) ----------------
__global__ void __launch_bounds__(256) gather_k(const float* __restrict__ epsPtr, int layer)
{
    const int node = blockIdx.x * 8 + (threadIdx.x >> 5);
    if (node >= NN) return;
    const int lane = threadIdx.x & 31;
    const float oe = 1.0f + epsPtr[layer];
    const float4 hv = *(const float4*)(&g_h[(size_t)node * 128 + lane * 4]);
    float4 acc = make_float4(oe * hv.x, oe * hv.y, oe * hv.z, oe * hv.w);
    const int rp0 = g_rowptr[node], rp1 = g_rowptr[node + 1];
    int e = rp0;
    for (; e + 3 < rp1; e += 4) {
        const int s0 = g_csr[e], s1 = g_csr[e + 1], s2 = g_csr[e + 2], s3 = g_csr[e + 3];
        const float4 v0 = *(const float4*)(&g_h[(size_t)s0 * 128 + lane * 4]);
        const float4 v1 = *(const float4*)(&g_h[(size_t)s1 * 128 + lane * 4]);
        const float4 v2 = *(const float4*)(&g_h[(size_t)s2 * 128 + lane * 4]);
        const float4 v3 = *(const float4*)(&g_h[(size_t)s3 * 128 + lane * 4]);
        acc.x += v0.x + v1.x + v2.x + v3.x;
        acc.y += v0.y + v1.y + v2.y + v3.y;
        acc.z += v0.z + v1.z + v2.z + v3.z;
        acc.w += v0.w + v1.w + v2.w + v3.w;
    }
    for (; e < rp1; e++) {
        const int s = g_csr[e];
        const float4 v = *(const float4*)(&g_h[(size_t)s * 128 + lane * 4]);
        acc.x += v.x; acc.y += v.y; acc.z += v.z; acc.w += v.w;
    }
    *(float4*)(&g_agg[(size_t)node * 128 + lane * 4]) = acc;
}

// ---------------- partitioned pooling: grid (NG, NPART) ----------------
// UPDATE: h += relu(y2*sc+sh) first (sc/sh from stats slot sIn + gam/bet),
// then pooled[g] += partial sum of h over this partition's rows.
template <bool UPDATE>
__global__ void __launch_bounds__(256) pool2_k(const float* __restrict__ y2,
                                               const float* __restrict__ gam,
                                               const float* __restrict__ bet, int sIn,
                                               float* __restrict__ pooled)
{
    __shared__ float4 sm[8][32];
    __shared__ float s_sc[128], s_sh[128];
    const int g = blockIdx.x, part = blockIdx.y;
    const int lane = threadIdx.x & 31;
    const int w = threadIdx.x >> 5;

    if (UPDATE) {
        if (threadIdx.x < 128) {
            const float inv_n = 1.0f / (float)NN;
            const float m = g_cs[sIn][threadIdx.x] * inv_n;
            const float var = g_cq[sIn][threadIdx.x] * inv_n - m * m;
            const float s = gam[threadIdx.x] * rsqrtf(var + 1e-5f);
            s_sc[threadIdx.x] = s;
            s_sh[threadIdx.x] = bet[threadIdx.x] - m * s;
        }
        __syncthreads();
    }
    const int beg = g_goff[g], end = g_goff[g + 1];

    float4 scv, shv;
    if (UPDATE) {
        scv = *(const float4*)(&s_sc[lane * 4]);
        shv = *(const float4*)(&s_sh[lane * 4]);
    }
    float4 acc = make_float4(0.f, 0.f, 0.f, 0.f);
    for (int r = beg + part * 8 + w; r < end; r += NPART * 8) {
        float4 hv = *(const float4*)(&g_h[(size_t)r * 128 + lane * 4]);
        if (UPDATE) {
            const float4 yv = *(const float4*)(&y2[(size_t)r * 128 + lane * 4]);
            hv.x += fmaxf(fmaf(yv.x, scv.x, shv.x), 0.f);
            hv.y += fmaxf(fmaf(yv.y, scv.y, shv.y), 0.f);
            hv.z += fmaxf(fmaf(yv.z, scv.z, shv.z), 0.f);
            hv.w += fmaxf(fmaf(yv.w, scv.w, shv.w), 0.f);
            *(float4*)(&g_h[(size_t)r * 128 + lane * 4]) = hv;
        }
        acc.x += hv.x; acc.y += hv.y; acc.z += hv.z; acc.w += hv.w;
    }
    sm[w][lane] = acc;
    __syncthreads();
    if (w == 0) {
        float4 t = sm[0][lane];
#pragma unroll
        for (int i = 1; i < 8; i++) {
            const float4 u = sm[i][lane];
            t.x += u.x; t.y += u.y; t.z += u.z; t.w += u.w;
        }
        atomicAdd((float4*)(&pooled[(size_t)g * 128 + lane * 4]), t);
    }
}

// ---------------- heads ----------------
__global__ void head_k(const float* __restrict__ pw, const float* __restrict__ pb,
                       float* __restrict__ out)
{
    const int g = blockIdx.x;
    const int c = threadIdx.x;
    if (c >= NC) return;
    const float cnt = (float)(g_goff[g + 1] - g_goff[g]);
    const float inv_cnt = 1.0f / fmaxf(cnt, 1.0f);
    float acc = 0.0f;
#pragma unroll
    for (int l = 0; l <= NL; l++) {
        const float* p = &g_pooled[(l * NG + g) * HID];
        float a = 0.0f;
#pragma unroll 8
        for (int f = 0; f < HID; f++)
            a = fmaf(p[f], pw[(l * HID + f) * NC + c], a);
        acc += a * inv_cnt + pb[l * NC + c];
    }
    out[g * NC + c] = acc;
}

// ---------------- launch ----------------
extern "C" void kernel_launch(void* const* d_in, const int* in_sizes, int n_in,
                              void* d_out, int out_size)
{
    const float* x     = (const float*)d_in[0];
    const int*   ei    = (const int*)d_in[1];
    const int*   batch = (const int*)d_in[2];
    const float* emb_w = (const float*)d_in[3];
    const float* emb_b = (const float*)d_in[4];
    const float* eps   = (const float*)d_in[5];
    const float* w1    = (const float*)d_in[6];
    const float* b1    = (const float*)d_in[7];
    const float* bn1g  = (const float*)d_in[8];
    const float* bn1b  = (const float*)d_in[9];
    const float* w2    = (const float*)d_in[10];
    const float* b2    = (const float*)d_in[11];
    const float* bng   = (const float*)d_in[12];
    const float* bnb   = (const float*)d_in[13];
    const float* pw    = (const float*)d_in[14];
    const float* pb    = (const float*)d_in[15];
    float*       out   = (float*)d_out;

    void *p_h, *p_agg, *p_y1, *p_y2, *p_pooled, *p_cs, *p_cq, *p_cnt;
    cudaGetSymbolAddress(&p_h,      g_h);
    cudaGetSymbolAddress(&p_agg,    g_agg);
    cudaGetSymbolAddress(&p_y1,     g_y1);
    cudaGetSymbolAddress(&p_y2,     g_y2);
    cudaGetSymbolAddress(&p_pooled, g_pooled);
    cudaGetSymbolAddress(&p_cs,     g_cs);
    cudaGetSymbolAddress(&p_cq,     g_cq);
    cudaGetSymbolAddress(&p_cnt,    g_cnt);

    cudaFuncSetAttribute(tgemm_k<0, false>, cudaFuncAttributeMaxDynamicSharedMemorySize, SM_TOT);
    cudaFuncSetAttribute(tgemm_k<0, true>,  cudaFuncAttributeMaxDynamicSharedMemorySize, SM_TOT);
    cudaFuncSetAttribute(tgemm_k<2, true>,  cudaFuncAttributeMaxDynamicSharedMemorySize, SM_TOT);

    cudaMemsetAsync(p_cs,     0, sizeof(float) * 2 * NL * HID);
    cudaMemsetAsync(p_cq,     0, sizeof(float) * 2 * NL * HID);
    cudaMemsetAsync(p_pooled, 0, sizeof(float) * (NL + 1) * NG * HID);
    cudaMemsetAsync(p_cnt,    0, sizeof(int) * NN);

    // pre-split all 9 weights: m=0 emb, m=1+2l w1[l], m=2+2l w2[l]
    wconv_k<<<dim3(16, NW), 1024>>>(emb_w, w1, w2);

    // CSR build (by dst, storing src) + graph boundaries
    hist_k<<<(NE + 255) / 256, 256>>>(ei + NE);
    scan_k<<<1, 1024>>>();
    fill_k<<<(NE + 255) / 256, 256>>>(ei, ei + NE);
    goff_k<<<(NN + 255) / 256, 256>>>(batch);

    const int GB = (NN + 63) / 64;

    // embedding
    tgemm_k<0, false><<<GB, 256, SM_TOT>>>(x, nullptr, nullptr, 0,
                                           0, 0, emb_b, (float*)p_h, NN);
    pool2_k<false><<<dim3(NG, NPART), 256>>>(nullptr, nullptr, nullptr, 0, (float*)p_pooled);

    for (int l = 0; l < NL; l++) {
        gather_k<<<(NN + 7) / 8, 256>>>(eps, l);

        // y1 = agg @ w1 + b1, stats -> slot 2l
        tgemm_k<0, true><<<GB, 256, SM_TOT>>>((const float*)p_agg, nullptr, nullptr, 0,
                                              2 * l, 1 + 2 * l, b1 + l * HID,
                                              (float*)p_y1, NN);
        // y2 = relu(bn1(y1)) @ w2 + b2, bn from slot 2l, stats -> slot 2l+1
        tgemm_k<2, true><<<GB, 256, SM_TOT>>>((const float*)p_y1,
                                              bn1g + l * HID, bn1b + l * HID, 2 * l,
                                              2 * l + 1, 2 + 2 * l, b2 + l * HID,
                                              (float*)p_y2, NN);
        // h += relu(bn2(y2)); pool hidden[l+1]; bn from slot 2l+1
        pool2_k<true><<<dim3(NG, NPART), 256>>>((const float*)p_y2,
                                                bng + l * HID, bnb + l * HID, 2 * l + 1,
                                                (float*)p_pooled + (size_t)(l + 1) * NG * HID);
    }

    head_k<<<NG, 32>>>(pw, pb, out);
}